// round 7
// baseline (speedup 1.0000x reference)
#include <cuda_runtime.h>
#include <math.h>

#define NB 8
#define NG 512
#define NT 1024
#define NK 5
#define NC 3

#define TPB 256
#define WPB 8
#define TGT_PER_WARP 2
#define T_PER_BLOCK (WPB * TGT_PER_WARP)   // 16 targets per block

// smem layout (floats): rawh[7680] | sxs[512*4] | shs[512*4]  = 11776 floats = 47KB
#define RAWH_F   (NG * NK * NC)            // 7680
#define FINAL_F  (2 * NG * 4)              // 4096
#define SMEM_F   (RAWH_F + FINAL_F)        // 11776

__device__ __forceinline__ float ex2f(float x) {
    float y;
    asm("ex2.approx.ftz.f32 %0, %1;" : "=f"(y) : "f"(x));
    return y;
}

__device__ __forceinline__ float warp_sum(float v) {
    #pragma unroll
    for (int off = 16; off; off >>= 1)
        v += __shfl_xor_sync(0xffffffffu, v, off);
    return v;
}

__global__ __launch_bounds__(TPB)
void fused_kernel(const float* __restrict__ x_grid,
                  const float* __restrict__ h_grid,
                  const float* __restrict__ target_x,
                  const float* __restrict__ sigma,
                  const float* __restrict__ g_w,
                  const float* __restrict__ g_b,
                  float* __restrict__ out)
{
    __shared__ __align__(16) float smem_buf[SMEM_F];

    const int tid  = threadIdx.x;
    const int warp = tid >> 5;
    const int lane = tid & 31;
    const int b    = blockIdx.y;

    // ---- coefficients (tiny, every thread) ----
    float a2[NK][NC];
    #pragma unroll
    for (int k = 0; k < NK; k++)
        #pragma unroll
        for (int c = 0; c < NC; c++) {
            float s   = __expf(sigma[k * NC + c]) + 1e-6f;
            float inv = 1.0f / s;
            a2[k][c]  = -0.5f * 1.4426950408889634f * inv * inv;
        }
    bool uni = true;
    #pragma unroll
    for (int k = 1; k < NK; k++)
        #pragma unroll
        for (int c = 0; c < NC; c++)
            uni = uni && (a2[k][c] == a2[0][c]);

    float gw[NK];
    #pragma unroll
    for (int k = 0; k < NK; k++) gw[k] = g_w[k];

    const float* xg = x_grid + b * NG * NC;
    const float* hg = h_grid + b * NG * NK * NC;
    const int tbase = blockIdx.x * T_PER_BLOCK + warp * TGT_PER_WARP;
    const float* tp = target_x + (b * NT + tbase) * NC;
    const float bb  = g_b[0];

    float acc[TGT_PER_WARP][NC];
    #pragma unroll
    for (int j = 0; j < TGT_PER_WARP; j++)
        #pragma unroll
        for (int c = 0; c < NC; c++) acc[j][c] = 0.f;

    if (uni) {
        // ======== FAST PATH ========
        const float r0 = sqrtf(-a2[0][0]);
        const float r1 = sqrtf(-a2[0][1]);
        const float r2 = sqrtf(-a2[0][2]);

        float*  rawh  = smem_buf;                          // 7680 floats
        float4* sxs   = (float4*)(smem_buf + RAWH_F);      // 512 float4
        float4* shs   = sxs + NG;                          // 512 float4

        // Pass A: coalesced float4 copy of the h block (30KB)
        {
            const float4* hg4 = (const float4*)hg;         // 1920 float4
            float4* rh4 = (float4*)rawh;
            #pragma unroll 2
            for (int i = tid; i < RAWH_F / 4; i += TPB)
                rh4[i] = hg4[i];
        }
        __syncthreads();

        // Pass B: hsum from smem + scaled coords (x via cheap scalar LDG)
        #pragma unroll
        for (int rr = 0; rr < NG / TPB; rr++) {
            const int r = tid + rr * TPB;
            const float* hp = rawh + r * (NK * NC);
            float h0 = 0.f, h1 = 0.f, h2 = 0.f;
            #pragma unroll
            for (int k = 0; k < NK; k++) {
                h0 += gw[k] * hp[k * NC + 0];
                h1 += gw[k] * hp[k * NC + 1];
                h2 += gw[k] * hp[k * NC + 2];
            }
            const float* xp = xg + r * NC;
            sxs[r] = make_float4(xp[0] * r0, xp[1] * r1, xp[2] * r2, 0.f);
            shs[r] = make_float4(h0, h1, h2, 0.f);
        }

        // scaled targets
        float tc[TGT_PER_WARP][NC];
        #pragma unroll
        for (int j = 0; j < TGT_PER_WARP; j++) {
            tc[j][0] = tp[j * NC + 0] * r0;
            tc[j][1] = tp[j * NC + 1] * r1;
            tc[j][2] = tp[j * NC + 2] * r2;
        }
        __syncthreads();

        #pragma unroll 4
        for (int i = 0; i < NG / 32; i++) {
            const int g = i * 32 + lane;
            const float4 xv = sxs[g];
            const float4 hv = shs[g];
            #pragma unroll
            for (int j = 0; j < TGT_PER_WARP; j++) {
                float d;
                d = xv.x - tc[j][0]; acc[j][0] += hv.x * ex2f(d * (-d));
                d = xv.y - tc[j][1]; acc[j][1] += hv.y * ex2f(d * (-d));
                d = xv.z - tc[j][2]; acc[j][2] += hv.z * ex2f(d * (-d));
            }
        }
    } else {
        // ======== GENERAL PATH: per-(k,c) scales ========
        float (*sx)[NG] = (float(*)[NG])smem_buf;   // rows 0..2: x, 3..17: h*gw

        for (int idx = tid; idx < NG * NC; idx += TPB) {
            int g = idx / NC, c = idx - g * NC;
            sx[c][g] = xg[idx];
        }
        for (int idx = tid; idx < NG * NK * NC; idx += TPB) {
            int g = idx / (NK * NC);
            int r = idx - g * (NK * NC);    // r = k*NC + c
            sx[NC + r][g] = hg[idx] * gw[r / NC];
        }

        float tc[TGT_PER_WARP][NC];
        #pragma unroll
        for (int j = 0; j < TGT_PER_WARP; j++)
            #pragma unroll
            for (int c = 0; c < NC; c++)
                tc[j][c] = tp[j * NC + c];
        __syncthreads();

        for (int i = 0; i < NG / 32; i++) {
            const int g = i * 32 + lane;
            const float x0 = sx[0][g], x1 = sx[1][g], x2 = sx[2][g];
            float u[TGT_PER_WARP][NC];
            #pragma unroll
            for (int j = 0; j < TGT_PER_WARP; j++) {
                u[j][0] = (x0 - tc[j][0]) * (x0 - tc[j][0]);
                u[j][1] = (x1 - tc[j][1]) * (x1 - tc[j][1]);
                u[j][2] = (x2 - tc[j][2]) * (x2 - tc[j][2]);
            }
            #pragma unroll
            for (int k = 0; k < NK; k++) {
                const float h0 = sx[NC + k * NC + 0][g];
                const float h1 = sx[NC + k * NC + 1][g];
                const float h2 = sx[NC + k * NC + 2][g];
                #pragma unroll
                for (int j = 0; j < TGT_PER_WARP; j++) {
                    acc[j][0] += h0 * ex2f(a2[k][0] * u[j][0]);
                    acc[j][1] += h1 * ex2f(a2[k][1] * u[j][1]);
                    acc[j][2] += h2 * ex2f(a2[k][2] * u[j][2]);
                }
            }
        }
    }

    // ---- reductions + store ----
    #pragma unroll
    for (int j = 0; j < TGT_PER_WARP; j++)
        #pragma unroll
        for (int c = 0; c < NC; c++)
            acc[j][c] = warp_sum(acc[j][c]);

    if (lane == 0) {
        #pragma unroll
        for (int j = 0; j < TGT_PER_WARP; j++) {
            float* o = out + (b * NT + tbase + j) * NC;
            o[0] = acc[j][0] + bb;
            o[1] = acc[j][1] + bb;
            o[2] = acc[j][2] + bb;
        }
    }
}

extern "C" void kernel_launch(void* const* d_in, const int* in_sizes, int n_in,
                              void* d_out, int out_size)
{
    const float* x_grid   = (const float*)d_in[0];  // (8, 512, 3)
    const float* h_grid   = (const float*)d_in[1];  // (8, 512, 5, 3)
    const float* target_x = (const float*)d_in[2];  // (8, 1024, 3)
    const float* sigma    = (const float*)d_in[3];  // (5, 3)
    const float* g_w      = (const float*)d_in[4];  // (1, 5)
    const float* g_b      = (const float*)d_in[5];  // (1,)
    float* out = (float*)d_out;                     // (8, 1024, 3)

    dim3 grid(NT / T_PER_BLOCK, NB);   // 64 x 8 = 512 blocks
    fused_kernel<<<grid, TPB>>>(x_grid, h_grid, target_x, sigma, g_w, g_b, out);
}